// round 14
// baseline (speedup 1.0000x reference)
#include <cuda_runtime.h>
#include <cuda_fp16.h>
#include <math.h>
#include <stdint.h>

#define L   4096
#define H   1024
#define FF  512
#define NE  8
#define ROWS (L * 2)
#define BK  32
#define NSTG 4
#define ROWB 80                        // 32 halves data (64B) + 16B pad
#define STG_SZ (256 * ROWB)            // 128 A rows + 128 B rows = 20480B
#define SMEM_BYTES (NSTG * STG_SZ)     // 81920
#define BREG (128 * ROWB)
#define MAXT 72                        // max total m-tiles: 64 + (NE-1) ceiling slack

// ---------------- static scratch ----------------
__device__ int    g_count[NE];
__device__ int    g_fill[NE];
__device__ int    g_top[L * 2];
__device__ float  g_tprob[L * 2];
__device__ int    g_perm[ROWS];
__device__ float  g_prob[ROWS];
__device__ int    g_tile_e[MAXT];      // flattened m-tile map: expert (-1 = inactive)
__device__ int    g_tile_m[MAXT];      // m0 within expert
__device__ int    g_tile_off[MAXT];    // expert row offset
__device__ int    g_tile_cnt[MAXT];    // expert row count
__device__ __half g_act[(size_t)ROWS * FF];
__device__ __half x_h[(size_t)L * H];
__device__ __half w13_h[(size_t)NE * 1024 * H];
__device__ __half w2_h[(size_t)NE * H * FF];

// ---------------- helpers ----------------
__device__ __forceinline__ uint32_t smem_u32(const void* p) {
    uint32_t a;
    asm("{ .reg .u64 t; cvta.to.shared.u64 t, %1; cvt.u32.u64 %0, t; }" : "=r"(a) : "l"(p));
    return a;
}
__device__ __forceinline__ void ldsm4(uint32_t* r, uint32_t addr) {
    asm volatile("ldmatrix.sync.aligned.m8n8.x4.shared.b16 {%0,%1,%2,%3}, [%4];"
                 : "=r"(r[0]), "=r"(r[1]), "=r"(r[2]), "=r"(r[3]) : "r"(addr));
}
__device__ __forceinline__ void mma16(float* c, const uint32_t* a, uint32_t b0, uint32_t b1) {
    asm volatile(
        "mma.sync.aligned.m16n8k16.row.col.f32.f16.f16.f32 "
        "{%0,%1,%2,%3},{%4,%5,%6,%7},{%8,%9},{%0,%1,%2,%3};"
        : "+f"(c[0]), "+f"(c[1]), "+f"(c[2]), "+f"(c[3])
        : "r"(a[0]), "r"(a[1]), "r"(a[2]), "r"(a[3]), "r"(b0), "r"(b1));
}
__device__ __forceinline__ void cpa16(uint32_t dst, const void* src) {
    asm volatile("cp.async.cg.shared.global [%0], [%1], 16;" :: "r"(dst), "l"(src));
}
#define CP_COMMIT() asm volatile("cp.async.commit_group;")
#define CP_WAIT(N)  asm volatile("cp.async.wait_group %0;" :: "n"(N))

#define NX4   (L * H / 4)
#define NW134 (NE * 2 * FF * H / 4)
#define NW24  (NE * H * FF / 4)

// ---------------- prepA: convert w13 only (GEMM1-critical) ----------------
__global__ void prepA_kernel(const float4* __restrict__ w13, uint2* __restrict__ w13h) {
    int stride = gridDim.x * blockDim.x;
    for (int i = blockIdx.x * blockDim.x + threadIdx.x; i < NW134; i += stride) {
        float4 v = w13[i];
        __half2 h0 = __floats2half2_rn(v.x, v.y);
        __half2 h1 = __floats2half2_rn(v.z, v.w);
        uint2 o;
        o.x = *reinterpret_cast<uint32_t*>(&h0);
        o.y = *reinterpret_cast<uint32_t*>(&h1);
        w13h[i] = o;
    }
}

// ---------------- prepX: zero out + convert x ----------------
__global__ void prepX_kernel(float* __restrict__ out, const float4* __restrict__ x,
                             uint2* __restrict__ xh) {
    int stride = gridDim.x * blockDim.x;
    for (int i = blockIdx.x * blockDim.x + threadIdx.x; i < NX4; i += stride) {
        *(float4*)&out[(size_t)i * 4] = make_float4(0.f, 0.f, 0.f, 0.f);
        float4 v = x[i];
        __half2 h0 = __floats2half2_rn(v.x, v.y);
        __half2 h1 = __floats2half2_rn(v.z, v.w);
        uint2 o;
        o.x = *reinterpret_cast<uint32_t*>(&h0);
        o.y = *reinterpret_cast<uint32_t*>(&h1);
        xh[i] = o;
    }
}

// ---------------- prepW2: convert w2 (needed only by GEMM2) ----------------
__global__ void prepW2_kernel(const float4* __restrict__ w2, uint2* __restrict__ w2h) {
    int stride = gridDim.x * blockDim.x;
    for (int i = blockIdx.x * blockDim.x + threadIdx.x; i < NW24; i += stride) {
        float4 v = w2[i];
        __half2 h0 = __floats2half2_rn(v.x, v.y);
        __half2 h1 = __floats2half2_rn(v.z, v.w);
        uint2 o;
        o.x = *reinterpret_cast<uint32_t*>(&h0);
        o.y = *reinterpret_cast<uint32_t*>(&h1);
        w2h[i] = o;
    }
}

// ---------------- router: logits + top2 ----------------
__global__ void router_kernel(const float* __restrict__ x, const float* __restrict__ gw) {
    int gid  = blockIdx.x * blockDim.x + threadIdx.x;
    int tok  = gid >> 5;
    int lane = gid & 31;
    if (tok >= L) return;
    const float* xr = x + (size_t)tok * H;
    float acc[NE];
#pragma unroll
    for (int e = 0; e < NE; e++) acc[e] = 0.f;
    for (int h = lane; h < H; h += 32) {
        float xv = xr[h];
#pragma unroll
        for (int e = 0; e < NE; e++) acc[e] = fmaf(xv, gw[e * H + h], acc[e]);
    }
#pragma unroll
    for (int e = 0; e < NE; e++) {
#pragma unroll
        for (int o = 16; o > 0; o >>= 1) acc[e] += __shfl_xor_sync(0xffffffffu, acc[e], o);
    }
    if (lane == 0) {
        int i0 = 0;
#pragma unroll
        for (int e = 1; e < NE; e++) if (acc[e] > acc[i0]) i0 = e;
        int i1 = (i0 == 0) ? 1 : 0;
#pragma unroll
        for (int e = 0; e < NE; e++) if (e != i0 && acc[e] > acc[i1]) i1 = e;
        float m  = fmaxf(acc[i0], acc[i1]);
        float e0 = expf(acc[i0] - m), e1 = expf(acc[i1] - m);
        float inv = 1.f / (e0 + e1);
        g_top[tok * 2] = i0; g_top[tok * 2 + 1] = i1;
        g_tprob[tok * 2] = e0 * inv; g_tprob[tok * 2 + 1] = e1 * inv;
    }
}

// ---------------- count: histogram + flattened tile map ----------------
__global__ void count_kernel() {
    __shared__ int hist[NE];
    int tid = threadIdx.x;
    if (tid < NE) hist[tid] = 0;
    __syncthreads();
    for (int i = tid; i < L * 2; i += blockDim.x)
        atomicAdd(&hist[g_top[i]], 1);
    __syncthreads();
    if (tid < NE) { g_count[tid] = hist[tid]; g_fill[tid] = 0; }
    if (tid == 0) {
        int idx = 0, off = 0;
#pragma unroll
        for (int e = 0; e < NE; e++) {
            int c = hist[e];
            for (int m0 = 0; m0 < c; m0 += 128) {
                g_tile_e[idx] = e;
                g_tile_m[idx] = m0;
                g_tile_off[idx] = off;
                g_tile_cnt[idx] = c;
                idx++;
            }
            off += c;
        }
        for (; idx < MAXT; idx++) g_tile_e[idx] = -1;
    }
}

// ---------------- scatter: block-aggregated atomics, inline 8-expert prefix ----------------
__global__ void scatter_kernel() {
    __shared__ int lc[NE];
    __shared__ int base[NE];
    __shared__ int offs[NE];
    int tid = threadIdx.x;
    int tok = blockIdx.x * blockDim.x + tid;
    if (tid < NE) lc[tid] = 0;
    __syncthreads();
    int e0 = -1, e1 = -1, p0 = 0, p1 = 0;
    if (tok < L) {
        e0 = g_top[tok * 2];
        e1 = g_top[tok * 2 + 1];
        p0 = atomicAdd(&lc[e0], 1);
        p1 = atomicAdd(&lc[e1], 1);
    }
    __syncthreads();
    if (tid == 0) {
        int s = 0;
#pragma unroll
        for (int e = 0; e < NE; e++) { offs[e] = s; s += g_count[e]; }
    }
    if (tid < NE) base[tid] = atomicAdd(&g_fill[tid], lc[tid]);
    __syncthreads();
    if (tok < L) {
        int r0 = offs[e0] + base[e0] + p0;
        int r1 = offs[e1] + base[e1] + p1;
        g_perm[r0] = tok;
        g_perm[r1] = tok;
        g_prob[r0] = g_tprob[tok * 2];
        g_prob[r1] = g_tprob[tok * 2 + 1];
    }
}

// ================= GEMM1 fused SwiGLU: flat tiles, 128 thr, BK=32 =================
__global__ void __launch_bounds__(128) gemm1_kernel() {
    int t = blockIdx.y;
    int e = g_tile_e[t];
    if (e < 0) return;
    int m0  = g_tile_m[t];
    int off = g_tile_off[t];
    int cnt = g_tile_cnt[t];
    int n0  = blockIdx.x * 64;

    extern __shared__ char smem[];
    uint32_t sb = smem_u32(smem);

    int tid = threadIdx.x, lane = tid & 31, wid = tid >> 5;
    int wm = wid & 1, wn = wid >> 1;
    int grp = lane >> 2, thr = lane & 3;

    const __half* srcp[8];
    uint32_t dstoff[8];
    {
        int j = tid & 3, r0 = tid >> 2;
        const __half* W = w13_h + (size_t)e * 1024 * H;
#pragma unroll
        for (int i = 0; i < 8; i++) {
            int row = r0 + 32 * i;
            const __half* s;
            if (row < 128) {
                int rA = m0 + row; if (rA >= cnt) rA = m0;
                s = x_h + (size_t)g_perm[off + rA] * H;
            } else if (row < 192) {
                s = W + (size_t)(n0 + row - 128) * H;
            } else {
                s = W + (size_t)(512 + n0 + row - 192) * H;
            }
            srcp[i] = s + j * 8;
            dstoff[i] = (uint32_t)(row * ROWB + j * 16);
        }
    }

#define G_FILL(S, K0)                                          \
    {                                                          \
        uint32_t bb = sb + (S) * STG_SZ;                       \
        _Pragma("unroll")                                      \
        for (int i = 0; i < 8; i++)                            \
            cpa16(bb + dstoff[i], srcp[i] + (K0));             \
    }

    uint32_t aoff = (uint32_t)((lane & 15) * ROWB + (lane >> 4) * 16);
    uint32_t boff = (uint32_t)((((lane >> 4) * 8 + (lane & 7)) * ROWB) + (((lane >> 3) & 1) * 16));

    float cg[4][4][4], cu[4][4][4];
#pragma unroll
    for (int i = 0; i < 4; i++)
#pragma unroll
        for (int j = 0; j < 4; j++)
#pragma unroll
            for (int k = 0; k < 4; k++) { cg[i][j][k] = 0.f; cu[i][j][k] = 0.f; }

    G_FILL(0, 0); CP_COMMIT();
    G_FILL(1, BK); CP_COMMIT();
    G_FILL(2, 2 * BK); CP_COMMIT();

    const int NIT = H / BK;  // 32
    for (int it = 0; it < NIT; it++) {
        CP_WAIT(2);
        __syncthreads();
        int cur = it % NSTG;
        int kn = it + NSTG - 1;
        if (kn < NIT) { G_FILL(kn % NSTG, kn * BK); }
        CP_COMMIT();

        uint32_t sc = sb + cur * STG_SZ;
#pragma unroll
        for (int ks = 0; ks < 2; ks++) {
            uint32_t a[4][4];
#pragma unroll
            for (int mt = 0; mt < 4; mt++)
                ldsm4(a[mt], sc + (uint32_t)((wm * 64 + mt * 16) * ROWB + ks * 32) + aoff);
            uint32_t bg[2][4], bu[2][4];
#pragma unroll
            for (int nt16 = 0; nt16 < 2; nt16++) {
                ldsm4(bg[nt16], sc + BREG + (uint32_t)((wn * 32 + nt16 * 16) * ROWB + ks * 32) + boff);
                ldsm4(bu[nt16], sc + BREG + (uint32_t)((64 + wn * 32 + nt16 * 16) * ROWB + ks * 32) + boff);
            }
#pragma unroll
            for (int mt = 0; mt < 4; mt++) {
#pragma unroll
                for (int nt = 0; nt < 4; nt++) {
                    mma16(cg[mt][nt], a[mt], bg[nt >> 1][(nt & 1) * 2], bg[nt >> 1][(nt & 1) * 2 + 1]);
                    mma16(cu[mt][nt], a[mt], bu[nt >> 1][(nt & 1) * 2], bu[nt >> 1][(nt & 1) * 2 + 1]);
                }
            }
        }
    }

    // epilogue: act = silu(g)*u
#pragma unroll
    for (int mt = 0; mt < 4; mt++) {
#pragma unroll
        for (int h2 = 0; h2 < 2; h2++) {
            int m = m0 + wm * 64 + mt * 16 + grp + h2 * 8;
            if (m < cnt) {
                size_t base = (size_t)(off + m) * FF;
#pragma unroll
                for (int nt = 0; nt < 4; nt++) {
                    int f = n0 + wn * 32 + nt * 8 + thr * 2;
                    float g0 = cg[mt][nt][h2 * 2 + 0], g1 = cg[mt][nt][h2 * 2 + 1];
                    float u0 = cu[mt][nt][h2 * 2 + 0], u1 = cu[mt][nt][h2 * 2 + 1];
                    float a0 = (g0 / (1.f + expf(-g0))) * u0;
                    float a1 = (g1 / (1.f + expf(-g1))) * u1;
                    *(__half2*)&g_act[base + f] = __floats2half2_rn(a0, a1);
                }
            }
        }
    }
}

// ================= GEMM2 + weighted combine: flat tiles, 128 thr, BK=32 =================
__global__ void __launch_bounds__(128) gemm2_kernel(float* __restrict__ out) {
    int t = blockIdx.y;
    int e = g_tile_e[t];
    if (e < 0) return;
    int m0  = g_tile_m[t];
    int off = g_tile_off[t];
    int cnt = g_tile_cnt[t];
    int n0  = blockIdx.x * 128;

    extern __shared__ char smem[];
    uint32_t sb = smem_u32(smem);

    int tid = threadIdx.x, lane = tid & 31, wid = tid >> 5;
    int wm = wid & 1, wn = wid >> 1;
    int grp = lane >> 2, thr = lane & 3;

    const __half* srcp[8];
    uint32_t dstoff[8];
    {
        int j = tid & 3, r0 = tid >> 2;
        const __half* W = w2_h + (size_t)e * H * FF;
#pragma unroll
        for (int i = 0; i < 8; i++) {
            int row = r0 + 32 * i;
            const __half* s;
            if (row < 128) {
                int rA = m0 + row; if (rA >= cnt) rA = m0;
                s = g_act + (size_t)(off + rA) * FF;
            } else {
                s = W + (size_t)(n0 + row - 128) * FF;
            }
            srcp[i] = s + j * 8;
            dstoff[i] = (uint32_t)(row * ROWB + j * 16);
        }
    }

    uint32_t aoff = (uint32_t)((lane & 15) * ROWB + (lane >> 4) * 16);
    uint32_t boff = (uint32_t)((((lane >> 4) * 8 + (lane & 7)) * ROWB) + (((lane >> 3) & 1) * 16));

    float acc[4][8][4];
#pragma unroll
    for (int i = 0; i < 4; i++)
#pragma unroll
        for (int j = 0; j < 8; j++)
#pragma unroll
            for (int k = 0; k < 4; k++) acc[i][j][k] = 0.f;

    G_FILL(0, 0); CP_COMMIT();
    G_FILL(1, BK); CP_COMMIT();
    G_FILL(2, 2 * BK); CP_COMMIT();

    const int NIT = FF / BK;  // 16
    for (int it = 0; it < NIT; it++) {
        CP_WAIT(2);
        __syncthreads();
        int cur = it % NSTG;
        int kn = it + NSTG - 1;
        if (kn < NIT) { G_FILL(kn % NSTG, kn * BK); }
        CP_COMMIT();

        uint32_t sc = sb + cur * STG_SZ;
#pragma unroll
        for (int ks = 0; ks < 2; ks++) {
            uint32_t a[4][4];
#pragma unroll
            for (int mt = 0; mt < 4; mt++)
                ldsm4(a[mt], sc + (uint32_t)((wm * 64 + mt * 16) * ROWB + ks * 32) + aoff);
            uint32_t b[4][4];
#pragma unroll
            for (int nt16 = 0; nt16 < 4; nt16++)
                ldsm4(b[nt16], sc + BREG + (uint32_t)((wn * 64 + nt16 * 16) * ROWB + ks * 32) + boff);
#pragma unroll
            for (int mt = 0; mt < 4; mt++) {
#pragma unroll
                for (int nt = 0; nt < 8; nt++)
                    mma16(acc[mt][nt], a[mt], b[nt >> 1][(nt & 1) * 2], b[nt >> 1][(nt & 1) * 2 + 1]);
            }
        }
    }

    // weighted combine: exactly 2 contributions per token element -> atomicAdd
#pragma unroll
    for (int mt = 0; mt < 4; mt++) {
#pragma unroll
        for (int h2 = 0; h2 < 2; h2++) {
            int m = m0 + wm * 64 + mt * 16 + grp + h2 * 8;
            if (m < cnt) {
                int   r   = off + m;
                int   tok = g_perm[r];
                float p   = g_prob[r];
                float* o  = out + (size_t)tok * H;
#pragma unroll
                for (int nt = 0; nt < 8; nt++) {
                    int n = n0 + wn * 64 + nt * 8 + thr * 2;
                    atomicAdd(&o[n],     p * acc[mt][nt][h2 * 2 + 0]);
                    atomicAdd(&o[n + 1], p * acc[mt][nt][h2 * 2 + 1]);
                }
            }
        }
    }
}

// ---------------- launch: fork-join across streams (graph-capturable) ----------------
extern "C" void kernel_launch(void* const* d_in, const int* in_sizes, int n_in,
                              void* d_out, int out_size) {
    const float* x   = (const float*)d_in[0];
    const float* gw  = (const float*)d_in[1];
    const float* w13 = (const float*)d_in[2];
    const float* w2  = (const float*)d_in[3];
    float* out = (float*)d_out;

    __half* xh;   cudaGetSymbolAddress((void**)&xh,   x_h);
    __half* w13h; cudaGetSymbolAddress((void**)&w13h, w13_h);
    __half* w2h;  cudaGetSymbolAddress((void**)&w2h,  w2_h);

    static cudaStream_t sB = nullptr, sC = nullptr;
    static cudaEvent_t  evFork = nullptr, evB = nullptr, evC1 = nullptr, evC2 = nullptr;
    if (sB == nullptr) {
        cudaStreamCreateWithFlags(&sB, cudaStreamNonBlocking);
        cudaStreamCreateWithFlags(&sC, cudaStreamNonBlocking);
        cudaEventCreateWithFlags(&evFork, cudaEventDisableTiming);
        cudaEventCreateWithFlags(&evB,    cudaEventDisableTiming);
        cudaEventCreateWithFlags(&evC1,   cudaEventDisableTiming);
        cudaEventCreateWithFlags(&evC2,   cudaEventDisableTiming);
        cudaFuncSetAttribute(gemm1_kernel, cudaFuncAttributeMaxDynamicSharedMemorySize, SMEM_BYTES);
        cudaFuncSetAttribute(gemm2_kernel, cudaFuncAttributeMaxDynamicSharedMemorySize, SMEM_BYTES);
    }

    // fork
    cudaEventRecord(evFork, 0);
    cudaStreamWaitEvent(sB, evFork, 0);
    cudaStreamWaitEvent(sC, evFork, 0);

    // main stream: w13 conversion (GEMM1-critical weights)
    prepA_kernel<<<2048, 256>>>((const float4*)w13, (uint2*)w13h);
    // branch B: routing chain (fp32 x/gw; deterministic counters + tile map)
    router_kernel<<<(L * 32 + 255) / 256, 256, 0, sB>>>(x, gw);
    count_kernel<<<1, 256, 0, sB>>>();
    scatter_kernel<<<(L + 255) / 256, 256, 0, sB>>>();
    cudaEventRecord(evB, sB);
    // branch C: zero out + x conversion (before GEMM1), then w2 (before GEMM2)
    prepX_kernel<<<1024, 256, 0, sC>>>(out, (const float4*)x, (uint2*)xh);
    cudaEventRecord(evC1, sC);
    prepW2_kernel<<<512, 256, 0, sC>>>((const float4*)w2, (uint2*)w2h);
    cudaEventRecord(evC2, sC);

    // join B + C1 before GEMM1
    cudaStreamWaitEvent(0, evB, 0);
    cudaStreamWaitEvent(0, evC1, 0);
    gemm1_kernel<<<dim3(FF / 64, MAXT), 128, SMEM_BYTES>>>();
    // join C2 before GEMM2
    cudaStreamWaitEvent(0, evC2, 0);
    gemm2_kernel<<<dim3(H / 128, MAXT), 128, SMEM_BYTES>>>(out);
}

// round 15
// speedup vs baseline: 1.0229x; 1.0229x over previous
#include <cuda_runtime.h>
#include <cuda_fp16.h>
#include <math.h>
#include <stdint.h>

#define L   4096
#define H   1024
#define FF  512
#define NE  8
#define ROWS (L * 2)
#define BK  32
#define NSTG 4
#define ROWB 80                        // 32 halves data (64B) + 16B pad
#define STG_SZ (256 * ROWB)            // 128 A rows + 128 B rows = 20480B
#define SMEM_BYTES (NSTG * STG_SZ)     // 81920
#define BREG (128 * ROWB)

// ---------------- static scratch ----------------
__device__ int    g_count[NE];
__device__ int    g_fill[NE];
__device__ int    g_top[L * 2];
__device__ float  g_tprob[L * 2];
__device__ int    g_perm[ROWS];
__device__ float  g_prob[ROWS];
__device__ __half g_act[(size_t)ROWS * FF];
__device__ __half x_h[(size_t)L * H];
__device__ __half w13_h[(size_t)NE * 1024 * H];
__device__ __half w2_h[(size_t)NE * H * FF];

// ---------------- helpers ----------------
__device__ __forceinline__ uint32_t smem_u32(const void* p) {
    uint32_t a;
    asm("{ .reg .u64 t; cvta.to.shared.u64 t, %1; cvt.u32.u64 %0, t; }" : "=r"(a) : "l"(p));
    return a;
}
__device__ __forceinline__ void ldsm4(uint32_t* r, uint32_t addr) {
    asm volatile("ldmatrix.sync.aligned.m8n8.x4.shared.b16 {%0,%1,%2,%3}, [%4];"
                 : "=r"(r[0]), "=r"(r[1]), "=r"(r[2]), "=r"(r[3]) : "r"(addr));
}
__device__ __forceinline__ void mma16(float* c, const uint32_t* a, uint32_t b0, uint32_t b1) {
    asm volatile(
        "mma.sync.aligned.m16n8k16.row.col.f32.f16.f16.f32 "
        "{%0,%1,%2,%3},{%4,%5,%6,%7},{%8,%9},{%0,%1,%2,%3};"
        : "+f"(c[0]), "+f"(c[1]), "+f"(c[2]), "+f"(c[3])
        : "r"(a[0]), "r"(a[1]), "r"(a[2]), "r"(a[3]), "r"(b0), "r"(b1));
}
__device__ __forceinline__ void cpa16(uint32_t dst, const void* src) {
    asm volatile("cp.async.cg.shared.global [%0], [%1], 16;" :: "r"(dst), "l"(src));
}
#define CP_COMMIT() asm volatile("cp.async.commit_group;")
#define CP_WAIT(N)  asm volatile("cp.async.wait_group %0;" :: "n"(N))

#define NX4   (L * H / 4)
#define NW134 (NE * 2 * FF * H / 4)
#define NW24  (NE * H * FF / 4)

__device__ __forceinline__ uint2 cvt4(float4 v) {
    __half2 h0 = __floats2half2_rn(v.x, v.y);
    __half2 h1 = __floats2half2_rn(v.z, v.w);
    uint2 o;
    o.x = *reinterpret_cast<uint32_t*>(&h0);
    o.y = *reinterpret_cast<uint32_t*>(&h1);
    return o;
}

// ---------------- prepA: convert w13 (GEMM1-critical), 2x unrolled ----------------
__global__ void prepA_kernel(const float4* __restrict__ w13, uint2* __restrict__ w13h) {
    int i = (blockIdx.x * blockDim.x + threadIdx.x) * 2;
    int stride = gridDim.x * blockDim.x * 2;
    for (; i < NW134; i += stride) {
        float4 v0 = w13[i];
        float4 v1 = w13[i + 1];
        w13h[i]     = cvt4(v0);
        w13h[i + 1] = cvt4(v1);
    }
}

// ---------------- prepX: convert x (GEMM1-critical), 2x unrolled ----------------
__global__ void prepX_kernel(const float4* __restrict__ x, uint2* __restrict__ xh) {
    int i = (blockIdx.x * blockDim.x + threadIdx.x) * 2;
    int stride = gridDim.x * blockDim.x * 2;
    for (; i < NX4; i += stride) {
        float4 v0 = x[i];
        float4 v1 = x[i + 1];
        xh[i]     = cvt4(v0);
        xh[i + 1] = cvt4(v1);
    }
}

// ---------------- prepW2: zero out + convert w2 (GEMM2-only), 2x unrolled ----------------
// NX4 == NW24 == L*H/4, so one index space covers both jobs.
__global__ void prepW2_kernel(float* __restrict__ out,
                              const float4* __restrict__ w2, uint2* __restrict__ w2h) {
    int i = (blockIdx.x * blockDim.x + threadIdx.x) * 2;
    int stride = gridDim.x * blockDim.x * 2;
    const float4 z = make_float4(0.f, 0.f, 0.f, 0.f);
    for (; i < NW24; i += stride) {
        float4 v0 = w2[i];
        float4 v1 = w2[i + 1];
        *(float4*)&out[(size_t)i * 4]       = z;
        *(float4*)&out[(size_t)(i + 1) * 4] = z;
        w2h[i]     = cvt4(v0);
        w2h[i + 1] = cvt4(v1);
    }
}

// ---------------- router: logits + top2; zeroes g_fill for scatter ----------------
__global__ void router_kernel(const float* __restrict__ x, const float* __restrict__ gw) {
    int gid  = blockIdx.x * blockDim.x + threadIdx.x;
    if (gid < NE) g_fill[gid] = 0;   // scatter runs strictly after router on this stream
    int tok  = gid >> 5;
    int lane = gid & 31;
    if (tok >= L) return;
    const float* xr = x + (size_t)tok * H;
    float acc[NE];
#pragma unroll
    for (int e = 0; e < NE; e++) acc[e] = 0.f;
    for (int h = lane; h < H; h += 32) {
        float xv = xr[h];
#pragma unroll
        for (int e = 0; e < NE; e++) acc[e] = fmaf(xv, gw[e * H + h], acc[e]);
    }
#pragma unroll
    for (int e = 0; e < NE; e++) {
#pragma unroll
        for (int o = 16; o > 0; o >>= 1) acc[e] += __shfl_xor_sync(0xffffffffu, acc[e], o);
    }
    if (lane == 0) {
        int i0 = 0;
#pragma unroll
        for (int e = 1; e < NE; e++) if (acc[e] > acc[i0]) i0 = e;
        int i1 = (i0 == 0) ? 1 : 0;
#pragma unroll
        for (int e = 0; e < NE; e++) if (e != i0 && acc[e] > acc[i1]) i1 = e;
        float m  = fmaxf(acc[i0], acc[i1]);
        float e0 = expf(acc[i0] - m), e1 = expf(acc[i1] - m);
        float inv = 1.f / (e0 + e1);
        g_top[tok * 2] = i0; g_top[tok * 2 + 1] = i1;
        g_tprob[tok * 2] = e0 * inv; g_tprob[tok * 2 + 1] = e1 * inv;
    }
}

// ---------------- scatter: per-block full histogram, aggregated atomics ----------------
__global__ void scatter_kernel() {
    __shared__ int hist[NE];
    __shared__ int lc[NE];
    __shared__ int base[NE];
    __shared__ int offs[NE];
    int tid = threadIdx.x;
    int tok = blockIdx.x * blockDim.x + tid;
    if (tid < NE) { hist[tid] = 0; lc[tid] = 0; }
    __syncthreads();
    // full histogram (L2-hot scan of g_top) + this block's local counts
    for (int i = tid; i < L * 2; i += blockDim.x)
        atomicAdd(&hist[g_top[i]], 1);
    int e0 = -1, e1 = -1, p0 = 0, p1 = 0;
    if (tok < L) {
        e0 = g_top[tok * 2];
        e1 = g_top[tok * 2 + 1];
        p0 = atomicAdd(&lc[e0], 1);
        p1 = atomicAdd(&lc[e1], 1);
    }
    __syncthreads();
    if (tid == 0) {
        int s = 0;
#pragma unroll
        for (int e = 0; e < NE; e++) { offs[e] = s; s += hist[e]; }
    }
    if (tid < NE) {
        base[tid] = atomicAdd(&g_fill[tid], lc[tid]);
        g_count[tid] = hist[tid];   // identical values from every block (deterministic)
    }
    __syncthreads();
    if (tok < L) {
        int r0 = offs[e0] + base[e0] + p0;
        int r1 = offs[e1] + base[e1] + p1;
        g_perm[r0] = tok;
        g_perm[r1] = tok;
        g_prob[r0] = g_tprob[tok * 2];
        g_prob[r1] = g_tprob[tok * 2 + 1];
    }
}

// inline expert offset/count from g_count
__device__ __forceinline__ void expert_range(int e, int& off, int& cnt) {
    off = 0; cnt = 0;
#pragma unroll
    for (int q = 0; q < NE; q++) {
        int c = g_count[q];
        if (q < e) off += c;
        if (q == e) cnt = c;
    }
}

// ================= GEMM1 fused SwiGLU: 128 thr, BK=32, warp tile 64x(32g+32u) =================
__global__ void __launch_bounds__(128) gemm1_kernel() {
    int e = blockIdx.z;
    int off, cnt;
    expert_range(e, off, cnt);
    int m0 = blockIdx.y * 128;
    if (m0 >= cnt) return;
    int n0 = blockIdx.x * 64;

    extern __shared__ char smem[];
    uint32_t sb = smem_u32(smem);

    int tid = threadIdx.x, lane = tid & 31, wid = tid >> 5;
    int wm = wid & 1, wn = wid >> 1;
    int grp = lane >> 2, thr = lane & 3;

    const __half* srcp[8];
    uint32_t dstoff[8];
    {
        int j = tid & 3, r0 = tid >> 2;
        const __half* W = w13_h + (size_t)e * 1024 * H;
#pragma unroll
        for (int i = 0; i < 8; i++) {
            int row = r0 + 32 * i;
            const __half* s;
            if (row < 128) {
                int rA = m0 + row; if (rA >= cnt) rA = m0;
                s = x_h + (size_t)g_perm[off + rA] * H;
            } else if (row < 192) {
                s = W + (size_t)(n0 + row - 128) * H;
            } else {
                s = W + (size_t)(512 + n0 + row - 192) * H;
            }
            srcp[i] = s + j * 8;
            dstoff[i] = (uint32_t)(row * ROWB + j * 16);
        }
    }

#define G_FILL(S, K0)                                          \
    {                                                          \
        uint32_t bb = sb + (S) * STG_SZ;                       \
        _Pragma("unroll")                                      \
        for (int i = 0; i < 8; i++)                            \
            cpa16(bb + dstoff[i], srcp[i] + (K0));             \
    }

    uint32_t aoff = (uint32_t)((lane & 15) * ROWB + (lane >> 4) * 16);
    uint32_t boff = (uint32_t)((((lane >> 4) * 8 + (lane & 7)) * ROWB) + (((lane >> 3) & 1) * 16));

    float cg[4][4][4], cu[4][4][4];
#pragma unroll
    for (int i = 0; i < 4; i++)
#pragma unroll
        for (int j = 0; j < 4; j++)
#pragma unroll
            for (int k = 0; k < 4; k++) { cg[i][j][k] = 0.f; cu[i][j][k] = 0.f; }

    G_FILL(0, 0); CP_COMMIT();
    G_FILL(1, BK); CP_COMMIT();
    G_FILL(2, 2 * BK); CP_COMMIT();

    const int NIT = H / BK;  // 32
    for (int it = 0; it < NIT; it++) {
        CP_WAIT(2);
        __syncthreads();
        int cur = it % NSTG;
        int kn = it + NSTG - 1;
        if (kn < NIT) { G_FILL(kn % NSTG, kn * BK); }
        CP_COMMIT();

        uint32_t sc = sb + cur * STG_SZ;
#pragma unroll
        for (int ks = 0; ks < 2; ks++) {
            uint32_t a[4][4];
#pragma unroll
            for (int mt = 0; mt < 4; mt++)
                ldsm4(a[mt], sc + (uint32_t)((wm * 64 + mt * 16) * ROWB + ks * 32) + aoff);
            uint32_t bg[2][4], bu[2][4];
#pragma unroll
            for (int nt16 = 0; nt16 < 2; nt16++) {
                ldsm4(bg[nt16], sc + BREG + (uint32_t)((wn * 32 + nt16 * 16) * ROWB + ks * 32) + boff);
                ldsm4(bu[nt16], sc + BREG + (uint32_t)((64 + wn * 32 + nt16 * 16) * ROWB + ks * 32) + boff);
            }
#pragma unroll
            for (int mt = 0; mt < 4; mt++) {
#pragma unroll
                for (int nt = 0; nt < 4; nt++) {
                    mma16(cg[mt][nt], a[mt], bg[nt >> 1][(nt & 1) * 2], bg[nt >> 1][(nt & 1) * 2 + 1]);
                    mma16(cu[mt][nt], a[mt], bu[nt >> 1][(nt & 1) * 2], bu[nt >> 1][(nt & 1) * 2 + 1]);
                }
            }
        }
    }

    // epilogue: act = silu(g)*u
#pragma unroll
    for (int mt = 0; mt < 4; mt++) {
#pragma unroll
        for (int h2 = 0; h2 < 2; h2++) {
            int m = m0 + wm * 64 + mt * 16 + grp + h2 * 8;
            if (m < cnt) {
                size_t base = (size_t)(off + m) * FF;
#pragma unroll
                for (int nt = 0; nt < 4; nt++) {
                    int f = n0 + wn * 32 + nt * 8 + thr * 2;
                    float g0 = cg[mt][nt][h2 * 2 + 0], g1 = cg[mt][nt][h2 * 2 + 1];
                    float u0 = cu[mt][nt][h2 * 2 + 0], u1 = cu[mt][nt][h2 * 2 + 1];
                    float a0 = (g0 / (1.f + expf(-g0))) * u0;
                    float a1 = (g1 / (1.f + expf(-g1))) * u1;
                    *(__half2*)&g_act[base + f] = __floats2half2_rn(a0, a1);
                }
            }
        }
    }
}

// ================= GEMM2 + weighted combine: 128 thr, BK=32, warp tile 64x64 =================
__global__ void __launch_bounds__(128) gemm2_kernel(float* __restrict__ out) {
    int e = blockIdx.z;
    int off, cnt;
    expert_range(e, off, cnt);
    int m0 = blockIdx.y * 128;
    if (m0 >= cnt) return;
    int n0 = blockIdx.x * 128;

    extern __shared__ char smem[];
    uint32_t sb = smem_u32(smem);

    int tid = threadIdx.x, lane = tid & 31, wid = tid >> 5;
    int wm = wid & 1, wn = wid >> 1;
    int grp = lane >> 2, thr = lane & 3;

    const __half* srcp[8];
    uint32_t dstoff[8];
    {
        int j = tid & 3, r0 = tid >> 2;
        const __half* W = w2_h + (size_t)e * H * FF;
#pragma unroll
        for (int i = 0; i < 8; i++) {
            int row = r0 + 32 * i;
            const __half* s;
            if (row < 128) {
                int rA = m0 + row; if (rA >= cnt) rA = m0;
                s = g_act + (size_t)(off + rA) * FF;
            } else {
                s = W + (size_t)(n0 + row - 128) * FF;
            }
            srcp[i] = s + j * 8;
            dstoff[i] = (uint32_t)(row * ROWB + j * 16);
        }
    }

    uint32_t aoff = (uint32_t)((lane & 15) * ROWB + (lane >> 4) * 16);
    uint32_t boff = (uint32_t)((((lane >> 4) * 8 + (lane & 7)) * ROWB) + (((lane >> 3) & 1) * 16));

    float acc[4][8][4];
#pragma unroll
    for (int i = 0; i < 4; i++)
#pragma unroll
        for (int j = 0; j < 8; j++)
#pragma unroll
            for (int k = 0; k < 4; k++) acc[i][j][k] = 0.f;

    G_FILL(0, 0); CP_COMMIT();
    G_FILL(1, BK); CP_COMMIT();
    G_FILL(2, 2 * BK); CP_COMMIT();

    const int NIT = FF / BK;  // 16
    for (int it = 0; it < NIT; it++) {
        CP_WAIT(2);
        __syncthreads();
        int cur = it % NSTG;
        int kn = it + NSTG - 1;
        if (kn < NIT) { G_FILL(kn % NSTG, kn * BK); }
        CP_COMMIT();

        uint32_t sc = sb + cur * STG_SZ;
#pragma unroll
        for (int ks = 0; ks < 2; ks++) {
            uint32_t a[4][4];
#pragma unroll
            for (int mt = 0; mt < 4; mt++)
                ldsm4(a[mt], sc + (uint32_t)((wm * 64 + mt * 16) * ROWB + ks * 32) + aoff);
            uint32_t b[4][4];
#pragma unroll
            for (int nt16 = 0; nt16 < 4; nt16++)
                ldsm4(b[nt16], sc + BREG + (uint32_t)((wn * 64 + nt16 * 16) * ROWB + ks * 32) + boff);
#pragma unroll
            for (int mt = 0; mt < 4; mt++) {
#pragma unroll
                for (int nt = 0; nt < 8; nt++)
                    mma16(acc[mt][nt], a[mt], b[nt >> 1][(nt & 1) * 2], b[nt >> 1][(nt & 1) * 2 + 1]);
            }
        }
    }

    // weighted combine: exactly 2 contributions per token element -> atomicAdd
#pragma unroll
    for (int mt = 0; mt < 4; mt++) {
#pragma unroll
        for (int h2 = 0; h2 < 2; h2++) {
            int m = m0 + wm * 64 + mt * 16 + grp + h2 * 8;
            if (m < cnt) {
                int   r   = off + m;
                int   tok = g_perm[r];
                float p   = g_prob[r];
                float* o  = out + (size_t)tok * H;
#pragma unroll
                for (int nt = 0; nt < 8; nt++) {
                    int n = n0 + wn * 64 + nt * 8 + thr * 2;
                    atomicAdd(&o[n],     p * acc[mt][nt][h2 * 2 + 0]);
                    atomicAdd(&o[n + 1], p * acc[mt][nt][h2 * 2 + 1]);
                }
            }
        }
    }
}

// ---------------- launch: fork-join across streams (graph-capturable) ----------------
extern "C" void kernel_launch(void* const* d_in, const int* in_sizes, int n_in,
                              void* d_out, int out_size) {
    const float* x   = (const float*)d_in[0];
    const float* gw  = (const float*)d_in[1];
    const float* w13 = (const float*)d_in[2];
    const float* w2  = (const float*)d_in[3];
    float* out = (float*)d_out;

    __half* xh;   cudaGetSymbolAddress((void**)&xh,   x_h);
    __half* w13h; cudaGetSymbolAddress((void**)&w13h, w13_h);
    __half* w2h;  cudaGetSymbolAddress((void**)&w2h,  w2_h);

    static cudaStream_t sB = nullptr, sC = nullptr;
    static cudaEvent_t  evFork = nullptr, evB = nullptr, evC1 = nullptr, evC2 = nullptr;
    if (sB == nullptr) {
        cudaStreamCreateWithFlags(&sB, cudaStreamNonBlocking);
        cudaStreamCreateWithFlags(&sC, cudaStreamNonBlocking);
        cudaEventCreateWithFlags(&evFork, cudaEventDisableTiming);
        cudaEventCreateWithFlags(&evB,    cudaEventDisableTiming);
        cudaEventCreateWithFlags(&evC1,   cudaEventDisableTiming);
        cudaEventCreateWithFlags(&evC2,   cudaEventDisableTiming);
        cudaFuncSetAttribute(gemm1_kernel, cudaFuncAttributeMaxDynamicSharedMemorySize, SMEM_BYTES);
        cudaFuncSetAttribute(gemm2_kernel, cudaFuncAttributeMaxDynamicSharedMemorySize, SMEM_BYTES);
    }

    // fork
    cudaEventRecord(evFork, 0);
    cudaStreamWaitEvent(sB, evFork, 0);
    cudaStreamWaitEvent(sC, evFork, 0);

    // main stream: w13 conversion (GEMM1-critical weights)
    prepA_kernel<<<2048, 256>>>((const float4*)w13, (uint2*)w13h);
    // branch B: routing chain (fp32 x/gw; scatter builds counts + permutation)
    router_kernel<<<(L * 32 + 255) / 256, 256, 0, sB>>>(x, gw);
    scatter_kernel<<<(L + 255) / 256, 256, 0, sB>>>();
    cudaEventRecord(evB, sB);
    // branch C: x conversion (before GEMM1), then out-zero + w2 (before GEMM2)
    prepX_kernel<<<1024, 256, 0, sC>>>((const float4*)x, (uint2*)xh);
    cudaEventRecord(evC1, sC);
    prepW2_kernel<<<1024, 256, 0, sC>>>(out, (const float4*)w2, (uint2*)w2h);
    cudaEventRecord(evC2, sC);

    // join B + C1 before GEMM1
    cudaStreamWaitEvent(0, evB, 0);
    cudaStreamWaitEvent(0, evC1, 0);
    gemm1_kernel<<<dim3(FF / 64, ROWS / 128, NE), 128, SMEM_BYTES>>>();
    // join C2 before GEMM2
    cudaStreamWaitEvent(0, evC2, 0);
    gemm2_kernel<<<dim3(H / 128, ROWS / 128, NE), 128, SMEM_BYTES>>>(out);
}

// round 17
// speedup vs baseline: 1.0687x; 1.0448x over previous
#include <cuda_runtime.h>
#include <cuda_fp16.h>
#include <math.h>
#include <stdint.h>

#define L   4096
#define H   1024
#define FF  512
#define NE  8
#define ROWS (L * 2)
#define BK  32
#define NSTG 4
#define ROWB 80                        // 32 halves data (64B) + 16B pad
#define STG_SZ (256 * ROWB)            // 128 A rows + 128 B rows = 20480B
#define SMEM_BYTES (NSTG * STG_SZ)     // 81920
#define BREG (128 * ROWB)

// ---------------- static scratch ----------------
__device__ int    g_count[NE];
__device__ int    g_fill[NE];
__device__ int    g_top[L * 2];
__device__ float  g_tprob[L * 2];
__device__ int    g_perm[ROWS];
__device__ float  g_prob[ROWS];
__device__ __half g_act[(size_t)ROWS * FF];
__device__ __half x_h[(size_t)L * H];
__device__ __half w13_h[(size_t)NE * 1024 * H];
__device__ __half w2_h[(size_t)NE * H * FF];

// ---------------- helpers ----------------
__device__ __forceinline__ uint32_t smem_u32(const void* p) {
    uint32_t a;
    asm("{ .reg .u64 t; cvta.to.shared.u64 t, %1; cvt.u32.u64 %0, t; }" : "=r"(a) : "l"(p));
    return a;
}
__device__ __forceinline__ void ldsm4(uint32_t* r, uint32_t addr) {
    asm volatile("ldmatrix.sync.aligned.m8n8.x4.shared.b16 {%0,%1,%2,%3}, [%4];"
                 : "=r"(r[0]), "=r"(r[1]), "=r"(r[2]), "=r"(r[3]) : "r"(addr));
}
__device__ __forceinline__ void mma16(float* c, const uint32_t* a, uint32_t b0, uint32_t b1) {
    asm volatile(
        "mma.sync.aligned.m16n8k16.row.col.f32.f16.f16.f32 "
        "{%0,%1,%2,%3},{%4,%5,%6,%7},{%8,%9},{%0,%1,%2,%3};"
        : "+f"(c[0]), "+f"(c[1]), "+f"(c[2]), "+f"(c[3])
        : "r"(a[0]), "r"(a[1]), "r"(a[2]), "r"(a[3]), "r"(b0), "r"(b1));
}
__device__ __forceinline__ void cpa16(uint32_t dst, const void* src) {
    asm volatile("cp.async.cg.shared.global [%0], [%1], 16;" :: "r"(dst), "l"(src));
}
#define CP_COMMIT() asm volatile("cp.async.commit_group;")
#define CP_WAIT(N)  asm volatile("cp.async.wait_group %0;" :: "n"(N))

#define NX4   (L * H / 4)
#define NW134 (NE * 2 * FF * H / 4)
#define NW24  (NE * H * FF / 4)

__device__ __forceinline__ uint2 cvt4(float4 v) {
    __half2 h0 = __floats2half2_rn(v.x, v.y);
    __half2 h1 = __floats2half2_rn(v.z, v.w);
    uint2 o;
    o.x = *reinterpret_cast<uint32_t*>(&h0);
    o.y = *reinterpret_cast<uint32_t*>(&h1);
    return o;
}

// ---------------- prepA: convert w13 (GEMM1-critical) ----------------
__global__ void prepA_kernel(const float4* __restrict__ w13, uint2* __restrict__ w13h) {
    int i = (blockIdx.x * blockDim.x + threadIdx.x) * 2;
    int stride = gridDim.x * blockDim.x * 2;
    for (; i < NW134; i += stride) {
        float4 v0 = w13[i];
        float4 v1 = w13[i + 1];
        w13h[i]     = cvt4(v0);
        w13h[i + 1] = cvt4(v1);
    }
}

// ---------------- prepX: convert x (GEMM1-critical) ----------------
__global__ void prepX_kernel(const float4* __restrict__ x, uint2* __restrict__ xh) {
    int i = (blockIdx.x * blockDim.x + threadIdx.x) * 2;
    int stride = gridDim.x * blockDim.x * 2;
    for (; i < NX4; i += stride) {
        float4 v0 = x[i];
        float4 v1 = x[i + 1];
        xh[i]     = cvt4(v0);
        xh[i + 1] = cvt4(v1);
    }
}

// ---------------- prepW2: zero out + convert w2 (GEMM2-only) ----------------
__global__ void prepW2_kernel(float* __restrict__ out,
                              const float4* __restrict__ w2, uint2* __restrict__ w2h) {
    int i = (blockIdx.x * blockDim.x + threadIdx.x) * 2;
    int stride = gridDim.x * blockDim.x * 2;
    const float4 z = make_float4(0.f, 0.f, 0.f, 0.f);
    for (; i < NW24; i += stride) {
        float4 v0 = w2[i];
        float4 v1 = w2[i + 1];
        *(float4*)&out[(size_t)i * 4]       = z;
        *(float4*)&out[(size_t)(i + 1) * 4] = z;
        w2h[i]     = cvt4(v0);
        w2h[i + 1] = cvt4(v1);
    }
}

// ---------------- router: logits + top2; zeroes g_fill for scatter ----------------
__global__ void router_kernel(const float* __restrict__ x, const float* __restrict__ gw) {
    int gid  = blockIdx.x * blockDim.x + threadIdx.x;
    if (gid < NE) g_fill[gid] = 0;
    int tok  = gid >> 5;
    int lane = gid & 31;
    if (tok >= L) return;
    const float* xr = x + (size_t)tok * H;
    float acc[NE];
#pragma unroll
    for (int e = 0; e < NE; e++) acc[e] = 0.f;
    for (int h = lane; h < H; h += 32) {
        float xv = xr[h];
#pragma unroll
        for (int e = 0; e < NE; e++) acc[e] = fmaf(xv, gw[e * H + h], acc[e]);
    }
#pragma unroll
    for (int e = 0; e < NE; e++) {
#pragma unroll
        for (int o = 16; o > 0; o >>= 1) acc[e] += __shfl_xor_sync(0xffffffffu, acc[e], o);
    }
    if (lane == 0) {
        int i0 = 0;
#pragma unroll
        for (int e = 1; e < NE; e++) if (acc[e] > acc[i0]) i0 = e;
        int i1 = (i0 == 0) ? 1 : 0;
#pragma unroll
        for (int e = 0; e < NE; e++) if (e != i0 && acc[e] > acc[i1]) i1 = e;
        float m  = fmaxf(acc[i0], acc[i1]);
        float e0 = expf(acc[i0] - m), e1 = expf(acc[i1] - m);
        float inv = 1.f / (e0 + e1);
        g_top[tok * 2] = i0; g_top[tok * 2 + 1] = i1;
        g_tprob[tok * 2] = e0 * inv; g_tprob[tok * 2 + 1] = e1 * inv;
    }
}

// ---------------- scatter: per-block full histogram, aggregated atomics ----------------
__global__ void scatter_kernel() {
    __shared__ int hist[NE];
    __shared__ int lc[NE];
    __shared__ int base[NE];
    __shared__ int offs[NE];
    int tid = threadIdx.x;
    int tok = blockIdx.x * blockDim.x + tid;
    if (tid < NE) { hist[tid] = 0; lc[tid] = 0; }
    __syncthreads();
    for (int i = tid; i < L * 2; i += blockDim.x)
        atomicAdd(&hist[g_top[i]], 1);
    int e0 = -1, e1 = -1, p0 = 0, p1 = 0;
    if (tok < L) {
        e0 = g_top[tok * 2];
        e1 = g_top[tok * 2 + 1];
        p0 = atomicAdd(&lc[e0], 1);
        p1 = atomicAdd(&lc[e1], 1);
    }
    __syncthreads();
    if (tid == 0) {
        int s = 0;
#pragma unroll
        for (int e = 0; e < NE; e++) { offs[e] = s; s += hist[e]; }
    }
    if (tid < NE) {
        base[tid] = atomicAdd(&g_fill[tid], lc[tid]);
        g_count[tid] = hist[tid];
    }
    __syncthreads();
    if (tok < L) {
        int r0 = offs[e0] + base[e0] + p0;
        int r1 = offs[e1] + base[e1] + p1;
        g_perm[r0] = tok;
        g_perm[r1] = tok;
        g_prob[r0] = g_tprob[tok * 2];
        g_prob[r1] = g_tprob[tok * 2 + 1];
    }
}

// inline expert offset/count from g_count
__device__ __forceinline__ void expert_range(int e, int& off, int& cnt) {
    off = 0; cnt = 0;
#pragma unroll
    for (int q = 0; q < NE; q++) {
        int c = g_count[q];
        if (q < e) off += c;
        if (q == e) cnt = c;
    }
}

// ================= GEMM1 fused SwiGLU: expert-group launch, 128 thr, BK=32 =================
__global__ void __launch_bounds__(128) gemm1_kernel(int ebase) {
    int e = ebase + blockIdx.z;
    int off, cnt;
    expert_range(e, off, cnt);
    int m0 = blockIdx.y * 128;
    if (m0 >= cnt) return;
    int n0 = blockIdx.x * 64;

    extern __shared__ char smem[];
    uint32_t sb = smem_u32(smem);

    int tid = threadIdx.x, lane = tid & 31, wid = tid >> 5;
    int wm = wid & 1, wn = wid >> 1;
    int grp = lane >> 2, thr = lane & 3;

    const __half* srcp[8];
    uint32_t dstoff[8];
    {
        int j = tid & 3, r0 = tid >> 2;
        const __half* W = w13_h + (size_t)e * 1024 * H;
#pragma unroll
        for (int i = 0; i < 8; i++) {
            int row = r0 + 32 * i;
            const __half* s;
            if (row < 128) {
                int rA = m0 + row; if (rA >= cnt) rA = m0;
                s = x_h + (size_t)g_perm[off + rA] * H;
            } else if (row < 192) {
                s = W + (size_t)(n0 + row - 128) * H;
            } else {
                s = W + (size_t)(512 + n0 + row - 192) * H;
            }
            srcp[i] = s + j * 8;
            dstoff[i] = (uint32_t)(row * ROWB + j * 16);
        }
    }

#define G_FILL(S, K0)                                          \
    {                                                          \
        uint32_t bb = sb + (S) * STG_SZ;                       \
        _Pragma("unroll")                                      \
        for (int i = 0; i < 8; i++)                            \
            cpa16(bb + dstoff[i], srcp[i] + (K0));             \
    }

    uint32_t aoff = (uint32_t)((lane & 15) * ROWB + (lane >> 4) * 16);
    uint32_t boff = (uint32_t)((((lane >> 4) * 8 + (lane & 7)) * ROWB) + (((lane >> 3) & 1) * 16));

    float cg[4][4][4], cu[4][4][4];
#pragma unroll
    for (int i = 0; i < 4; i++)
#pragma unroll
        for (int j = 0; j < 4; j++)
#pragma unroll
            for (int k = 0; k < 4; k++) { cg[i][j][k] = 0.f; cu[i][j][k] = 0.f; }

    G_FILL(0, 0); CP_COMMIT();
    G_FILL(1, BK); CP_COMMIT();
    G_FILL(2, 2 * BK); CP_COMMIT();

    const int NIT = H / BK;  // 32
    for (int it = 0; it < NIT; it++) {
        CP_WAIT(2);
        __syncthreads();
        int cur = it % NSTG;
        int kn = it + NSTG - 1;
        if (kn < NIT) { G_FILL(kn % NSTG, kn * BK); }
        CP_COMMIT();

        uint32_t sc = sb + cur * STG_SZ;
#pragma unroll
        for (int ks = 0; ks < 2; ks++) {
            uint32_t a[4][4];
#pragma unroll
            for (int mt = 0; mt < 4; mt++)
                ldsm4(a[mt], sc + (uint32_t)((wm * 64 + mt * 16) * ROWB + ks * 32) + aoff);
            uint32_t bg[2][4], bu[2][4];
#pragma unroll
            for (int nt16 = 0; nt16 < 2; nt16++) {
                ldsm4(bg[nt16], sc + BREG + (uint32_t)((wn * 32 + nt16 * 16) * ROWB + ks * 32) + boff);
                ldsm4(bu[nt16], sc + BREG + (uint32_t)((64 + wn * 32 + nt16 * 16) * ROWB + ks * 32) + boff);
            }
#pragma unroll
            for (int mt = 0; mt < 4; mt++) {
#pragma unroll
                for (int nt = 0; nt < 4; nt++) {
                    mma16(cg[mt][nt], a[mt], bg[nt >> 1][(nt & 1) * 2], bg[nt >> 1][(nt & 1) * 2 + 1]);
                    mma16(cu[mt][nt], a[mt], bu[nt >> 1][(nt & 1) * 2], bu[nt >> 1][(nt & 1) * 2 + 1]);
                }
            }
        }
    }

    // epilogue: act = silu(g)*u
#pragma unroll
    for (int mt = 0; mt < 4; mt++) {
#pragma unroll
        for (int h2 = 0; h2 < 2; h2++) {
            int m = m0 + wm * 64 + mt * 16 + grp + h2 * 8;
            if (m < cnt) {
                size_t base = (size_t)(off + m) * FF;
#pragma unroll
                for (int nt = 0; nt < 4; nt++) {
                    int f = n0 + wn * 32 + nt * 8 + thr * 2;
                    float g0 = cg[mt][nt][h2 * 2 + 0], g1 = cg[mt][nt][h2 * 2 + 1];
                    float u0 = cu[mt][nt][h2 * 2 + 0], u1 = cu[mt][nt][h2 * 2 + 1];
                    float a0 = (g0 / (1.f + expf(-g0))) * u0;
                    float a1 = (g1 / (1.f + expf(-g1))) * u1;
                    *(__half2*)&g_act[base + f] = __floats2half2_rn(a0, a1);
                }
            }
        }
    }
}

// ================= GEMM2 + weighted combine: expert-group launch, 128 thr, BK=32 =================
__global__ void __launch_bounds__(128) gemm2_kernel(int ebase, float* __restrict__ out) {
    int e = ebase + blockIdx.z;
    int off, cnt;
    expert_range(e, off, cnt);
    int m0 = blockIdx.y * 128;
    if (m0 >= cnt) return;
    int n0 = blockIdx.x * 128;

    extern __shared__ char smem[];
    uint32_t sb = smem_u32(smem);

    int tid = threadIdx.x, lane = tid & 31, wid = tid >> 5;
    int wm = wid & 1, wn = wid >> 1;
    int grp = lane >> 2, thr = lane & 3;

    const __half* srcp[8];
    uint32_t dstoff[8];
    {
        int j = tid & 3, r0 = tid >> 2;
        const __half* W = w2_h + (size_t)e * H * FF;
#pragma unroll
        for (int i = 0; i < 8; i++) {
            int row = r0 + 32 * i;
            const __half* s;
            if (row < 128) {
                int rA = m0 + row; if (rA >= cnt) rA = m0;
                s = g_act + (size_t)(off + rA) * FF;
            } else {
                s = W + (size_t)(n0 + row - 128) * FF;
            }
            srcp[i] = s + j * 8;
            dstoff[i] = (uint32_t)(row * ROWB + j * 16);
        }
    }

    uint32_t aoff = (uint32_t)((lane & 15) * ROWB + (lane >> 4) * 16);
    uint32_t boff = (uint32_t)((((lane >> 4) * 8 + (lane & 7)) * ROWB) + (((lane >> 3) & 1) * 16));

    float acc[4][8][4];
#pragma unroll
    for (int i = 0; i < 4; i++)
#pragma unroll
        for (int j = 0; j < 8; j++)
#pragma unroll
            for (int k = 0; k < 4; k++) acc[i][j][k] = 0.f;

    G_FILL(0, 0); CP_COMMIT();
    G_FILL(1, BK); CP_COMMIT();
    G_FILL(2, 2 * BK); CP_COMMIT();

    const int NIT = FF / BK;  // 16
    for (int it = 0; it < NIT; it++) {
        CP_WAIT(2);
        __syncthreads();
        int cur = it % NSTG;
        int kn = it + NSTG - 1;
        if (kn < NIT) { G_FILL(kn % NSTG, kn * BK); }
        CP_COMMIT();

        uint32_t sc = sb + cur * STG_SZ;
#pragma unroll
        for (int ks = 0; ks < 2; ks++) {
            uint32_t a[4][4];
#pragma unroll
            for (int mt = 0; mt < 4; mt++)
                ldsm4(a[mt], sc + (uint32_t)((wm * 64 + mt * 16) * ROWB + ks * 32) + aoff);
            uint32_t b[4][4];
#pragma unroll
            for (int nt16 = 0; nt16 < 4; nt16++)
                ldsm4(b[nt16], sc + BREG + (uint32_t)((wn * 64 + nt16 * 16) * ROWB + ks * 32) + boff);
#pragma unroll
            for (int mt = 0; mt < 4; mt++) {
#pragma unroll
                for (int nt = 0; nt < 8; nt++)
                    mma16(acc[mt][nt], a[mt], b[nt >> 1][(nt & 1) * 2], b[nt >> 1][(nt & 1) * 2 + 1]);
            }
        }
    }

    // weighted combine: exactly 2 contributions per token element -> atomicAdd
#pragma unroll
    for (int mt = 0; mt < 4; mt++) {
#pragma unroll
        for (int h2 = 0; h2 < 2; h2++) {
            int m = m0 + wm * 64 + mt * 16 + grp + h2 * 8;
            if (m < cnt) {
                int   r   = off + m;
                int   tok = g_perm[r];
                float p   = g_prob[r];
                float* o  = out + (size_t)tok * H;
#pragma unroll
                for (int nt = 0; nt < 8; nt++) {
                    int n = n0 + wn * 64 + nt * 8 + thr * 2;
                    atomicAdd(&o[n],     p * acc[mt][nt][h2 * 2 + 0]);
                    atomicAdd(&o[n + 1], p * acc[mt][nt][h2 * 2 + 1]);
                }
            }
        }
    }
}

// ---------------- launch: 2-group expert pipelining on the existing 2 streams ----------------
extern "C" void kernel_launch(void* const* d_in, const int* in_sizes, int n_in,
                              void* d_out, int out_size) {
    const float* x   = (const float*)d_in[0];
    const float* gw  = (const float*)d_in[1];
    const float* w13 = (const float*)d_in[2];
    const float* w2  = (const float*)d_in[3];
    float* out = (float*)d_out;

    __half* xh;   cudaGetSymbolAddress((void**)&xh,   x_h);
    __half* w13h; cudaGetSymbolAddress((void**)&w13h, w13_h);
    __half* w2h;  cudaGetSymbolAddress((void**)&w2h,  w2_h);

    static cudaStream_t sB = nullptr, sC = nullptr;
    static cudaEvent_t  evFork = nullptr, evA = nullptr, evB = nullptr,
                        evC1 = nullptr, evC2 = nullptr, evG1 = nullptr;
    if (sB == nullptr) {
        cudaStreamCreateWithFlags(&sB, cudaStreamNonBlocking);
        cudaStreamCreateWithFlags(&sC, cudaStreamNonBlocking);
        cudaEventCreateWithFlags(&evFork, cudaEventDisableTiming);
        cudaEventCreateWithFlags(&evA,    cudaEventDisableTiming);
        cudaEventCreateWithFlags(&evB,    cudaEventDisableTiming);
        cudaEventCreateWithFlags(&evC1,   cudaEventDisableTiming);
        cudaEventCreateWithFlags(&evC2,   cudaEventDisableTiming);
        cudaEventCreateWithFlags(&evG1,   cudaEventDisableTiming);
        cudaFuncSetAttribute(gemm1_kernel, cudaFuncAttributeMaxDynamicSharedMemorySize, SMEM_BYTES);
        cudaFuncSetAttribute(gemm2_kernel, cudaFuncAttributeMaxDynamicSharedMemorySize, SMEM_BYTES);
    }

    // fork
    cudaEventRecord(evFork, 0);
    cudaStreamWaitEvent(sB, evFork, 0);
    cudaStreamWaitEvent(sC, evFork, 0);

    // main stream: w13 conversion (GEMM1-critical weights)
    prepA_kernel<<<2048, 256>>>((const float4*)w13, (uint2*)w13h);
    cudaEventRecord(evA, 0);
    // branch B: routing chain
    router_kernel<<<(L * 32 + 255) / 256, 256, 0, sB>>>(x, gw);
    scatter_kernel<<<(L + 255) / 256, 256, 0, sB>>>();
    cudaEventRecord(evB, sB);
    // branch C: x conversion, then out-zero + w2
    prepX_kernel<<<1024, 256, 0, sC>>>((const float4*)x, (uint2*)xh);
    cudaEventRecord(evC1, sC);
    prepW2_kernel<<<1024, 256, 0, sC>>>(out, (const float4*)w2, (uint2*)w2h);
    cudaEventRecord(evC2, sC);

    // group 0 (experts 0-3) on stream 0: prepA in-stream; wait routing + x
    cudaStreamWaitEvent(0, evB, 0);
    cudaStreamWaitEvent(0, evC1, 0);
    gemm1_kernel<<<dim3(FF / 64, ROWS / 128, 4), 128, SMEM_BYTES>>>(0);
    cudaStreamWaitEvent(0, evC2, 0);
    gemm2_kernel<<<dim3(H / 128, ROWS / 128, 4), 128, SMEM_BYTES>>>(0, out);

    // group 1 (experts 4-7) on sB: scatter in-stream; wait w13 + x
    cudaStreamWaitEvent(sB, evA, 0);
    cudaStreamWaitEvent(sB, evC1, 0);
    gemm1_kernel<<<dim3(FF / 64, ROWS / 128, 4), 128, SMEM_BYTES, sB>>>(4);
    cudaStreamWaitEvent(sB, evC2, 0);
    gemm2_kernel<<<dim3(H / 128, ROWS / 128, 4), 128, SMEM_BYTES, sB>>>(4, out);
    cudaEventRecord(evG1, sB);

    // join group 1 back to the capture stream
    cudaStreamWaitEvent(0, evG1, 0);
}